// round 3
// baseline (speedup 1.0000x reference)
#include <cuda_runtime.h>
#include <cstdint>

// FastFood = fixed linear map: out = X (R x 64) * M^T, where
//   M[i][j] = c * S[i] * B[j] * sum_k (-1)^(popc(i&k)+popc(P[k]&j)) * G[k]
//   c = sqrt(1/8) * (1/8)
// Setup kernel builds M (rounded to tf32/RNA) once; main kernel is a
// tensor-core GEMM (mma.m16n8k8.tf32) — removes all shuffles from Round 1.

__device__ float g_M[64 * 64];

__global__ void setup_M(const float* __restrict__ B, const float* __restrict__ G,
                        const float* __restrict__ S, const int* __restrict__ P)
{
    int idx = blockIdx.x * blockDim.x + threadIdx.x;   // 0..4095
    if (idx >= 64 * 64) return;
    int i = idx >> 6;
    int j = idx & 63;

    float acc = 0.0f;
    #pragma unroll 8
    for (int k = 0; k < 64; k++) {
        int pk = __ldg(&P[k]);
        float g = __ldg(&G[k]);
        int par = (__popc(i & k) + __popc(pk & j)) & 1;
        acc += par ? -g : g;
    }
    const float c = 0.04419417382415922f;   // sqrt(1/8)/8
    float m = c * __ldg(&S[i]) * __ldg(&B[j]) * acc;

    // round-to-nearest tf32 so the B operand carries no truncation bias
    uint32_t mt;
    asm("cvt.rna.tf32.f32 %0, %1;" : "=r"(mt) : "f"(m));
    g_M[idx] = __uint_as_float(mt);
}

#define TILE      128          // rows per block
#define SMSTRIDE  68           // floats per smem row (64 + 4 pad -> conflict-free)

__global__ __launch_bounds__(256) void ff_mma(
    const float* __restrict__ x,
    float* __restrict__ out)
{
    __shared__ float sm[TILE * SMSTRIDE];      // 34816 B

    const int tid  = threadIdx.x;
    const int warp = tid >> 5;                 // 0..7 -> output cols [8w, 8w+8)
    const int lane = tid & 31;

    // ---- B fragments: 8 k-steps, 2 regs each, resident for the whole block ----
    // b0[k] = M[8w + lane/4][8k + lane%4], b1[k] = M[...][8k + lane%4 + 4]
    uint32_t b0[8], b1[8];
    {
        const float* Mrow = &g_M[(warp * 8 + (lane >> 2)) * 64 + (lane & 3)];
        #pragma unroll
        for (int k = 0; k < 8; k++) {
            b0[k] = __float_as_uint(Mrow[8 * k]);
            b1[k] = __float_as_uint(Mrow[8 * k + 4]);
        }
    }

    // ---- stage x tile (128 x 64 f32) into smem via cp.async.cg (16B) ----
    const float* src = x + (size_t)blockIdx.x * TILE * 64;
    {
        int r0 = tid >> 4;                     // 16 threads per row
        int c  = (tid & 15) << 2;              // float4 column
        #pragma unroll
        for (int p = 0; p < TILE / 16; p++) {  // 8 passes
            int r = r0 + (p << 4);
            uint32_t saddr = (uint32_t)__cvta_generic_to_shared(&sm[r * SMSTRIDE + c]);
            const float* g = src + r * 64 + c;
            asm volatile("cp.async.cg.shared.global [%0], [%1], 16;\n"
                         :: "r"(saddr), "l"(g));
        }
        asm volatile("cp.async.commit_group;\n");
        asm volatile("cp.async.wait_all;\n");
    }
    __syncthreads();

    // ---- per-thread ldmatrix row address (x4: 4 8x8-b32 matrices) ----
    // matrix q = lane/8:  q0: rows 0-7  cols +0 | q1: rows 8-15 cols +0
    //                     q2: rows 0-7  cols +4 | q3: rows 8-15 cols +4
    const int q    = lane >> 3;
    const int rr   = (lane & 7) + ((q & 1) << 3);
    const int cofs = (q >> 1) << 2;

    const int ncol      = warp * 8 + ((lane & 3) << 1);
    const int orow_base = blockIdx.x * TILE + (lane >> 2);

    #pragma unroll
    for (int m = 0; m < TILE / 16; m++) {      // 8 m-tiles of 16 rows
        float c0 = 0.f, c1 = 0.f, c2 = 0.f, c3 = 0.f;
        uint32_t abase =
            (uint32_t)__cvta_generic_to_shared(&sm[(m * 16 + rr) * SMSTRIDE + cofs]);

        #pragma unroll
        for (int k = 0; k < 8; k++) {          // 8 k-steps of 8
            uint32_t a0, a1, a2, a3;
            uint32_t addr = abase + k * 32;    // +8 floats per k-step
            asm volatile(
                "ldmatrix.sync.aligned.m8n8.x4.shared.b16 {%0,%1,%2,%3}, [%4];\n"
                : "=r"(a0), "=r"(a1), "=r"(a2), "=r"(a3) : "r"(addr));
            asm volatile(
                "mma.sync.aligned.m16n8k8.row.col.f32.tf32.tf32.f32 "
                "{%0,%1,%2,%3}, {%4,%5,%6,%7}, {%8,%9}, {%0,%1,%2,%3};\n"
                : "+f"(c0), "+f"(c1), "+f"(c2), "+f"(c3)
                : "r"(a0), "r"(a1), "r"(a2), "r"(a3), "r"(b0[k]), "r"(b1[k]));
        }

        // C frag: (row lane/4, cols 2(lane%4)+{0,1}) and (row+8, same cols)
        int orow = orow_base + m * 16;
        float2 v01 = make_float2(c0, c1);
        float2 v23 = make_float2(c2, c3);
        __stcs((float2*)&out[(size_t)orow * 64 + ncol], v01);
        __stcs((float2*)&out[(size_t)(orow + 8) * 64 + ncol], v23);
    }
}

extern "C" void kernel_launch(void* const* d_in, const int* in_sizes, int n_in,
                              void* d_out, int out_size)
{
    const float* x = (const float*)d_in[0];
    const float* B = (const float*)d_in[1];
    const float* G = (const float*)d_in[2];
    const float* S = (const float*)d_in[3];
    const int*   P = (const int*)d_in[4];
    float* out = (float*)d_out;

    int nrows  = in_sizes[0] / 64;     // 524288
    int ntiles = nrows / TILE;         // 4096

    setup_M<<<16, 256>>>(B, G, S, P);
    ff_mma<<<ntiles, 256>>>(x, out);
}